// round 1
// baseline (speedup 1.0000x reference)
#include <cuda_runtime.h>
#include <cstdint>

#define NN 100000
#define EE 1600000
#define IN_DIM 128
#define OUT_DIM 64
#define TT 8
#define EPS_ 1e-7f

// ---------------- scratch (no allocations allowed) ----------------
__device__ float g_hlin[(size_t)NN * OUT_DIM];   // x @ W
__device__ float g_hacc[(size_t)NN * OUT_DIM];   // scatter accumulator
__device__ float g_deg[NN];
__device__ float g_dinv[NN];

// ---------------- helpers ----------------
__device__ __forceinline__ float warp_sum(float v) {
#pragma unroll
    for (int o = 16; o > 0; o >>= 1) v += __shfl_xor_sync(0xffffffffu, v, o);
    return v;
}

__device__ __forceinline__ void red_add_v4(float* p, float a, float b, float c, float d) {
    asm volatile("red.global.add.v4.f32 [%0], {%1, %2, %3, %4};"
                 :: "l"(p), "f"(a), "f"(b), "f"(c), "f"(d) : "memory");
}

// ---------------- kernels ----------------

// zero h_acc, set deg = 1 (self loop)
__global__ void init_kernel() {
    int i = blockIdx.x * blockDim.x + threadIdx.x;
    if (i < NN * OUT_DIM) g_hacc[i] = 0.0f;
    if (i < NN) g_deg[i] = 1.0f;
}

__global__ void deg_kernel(const int* __restrict__ ei) {
    int e = blockIdx.x * blockDim.x + threadIdx.x;
    if (e >= EE) return;
    int d = ei[EE + e];
    atomicAdd(&g_deg[d], 1.0f);
}

__global__ void dinv_kernel() {
    int n = blockIdx.x * blockDim.x + threadIdx.x;
    if (n >= NN) return;
    g_dinv[n] = rsqrtf(fmaxf(g_deg[n], 1.0f));
}

// h_lin = x @ W  : one warp per node, W in smem
__global__ void gemm_kernel(const float* __restrict__ x, const float* __restrict__ W) {
    __shared__ float Ws[IN_DIM * OUT_DIM];
    int tid = threadIdx.x;
    for (int i = tid; i < IN_DIM * OUT_DIM; i += blockDim.x) Ws[i] = W[i];
    __syncthreads();

    int warp = (blockIdx.x * blockDim.x + tid) >> 5;
    int lane = tid & 31;
    if (warp >= NN) return;

    const float* xr = x + (size_t)warp * IN_DIM;
    float xv[4];
#pragma unroll
    for (int i = 0; i < 4; i++) xv[i] = xr[lane + 32 * i];

    float a0 = 0.0f, a1 = 0.0f;
#pragma unroll
    for (int k = 0; k < IN_DIM; k++) {
        float xk = __shfl_sync(0xffffffffu, xv[k >> 5], k & 31);
        a0 = fmaf(xk, Ws[k * OUT_DIM + lane], a0);
        a1 = fmaf(xk, Ws[k * OUT_DIM + lane + 32], a1);
    }
    g_hlin[(size_t)warp * OUT_DIM + lane] = a0;
    g_hlin[(size_t)warp * OUT_DIM + lane + 32] = a1;
}

// 16 threads per edge, each does one float4 slice, vector reduction into h_acc
__global__ void scatter_kernel(const int* __restrict__ ei) {
    long long gid = (long long)blockIdx.x * blockDim.x + threadIdx.x;
    int e = (int)(gid >> 4);
    int g = (int)(gid & 15);
    if (e >= EE) return;
    int s = ei[e];
    int d = ei[EE + e];
    float norm = g_dinv[s] * g_dinv[d];
    const float4 hv = *reinterpret_cast<const float4*>(g_hlin + (size_t)s * OUT_DIM + g * 4);
    red_add_v4(g_hacc + (size_t)d * OUT_DIM + g * 4,
               norm * hv.x, norm * hv.y, norm * hv.z, norm * hv.w);
}

// one warp per node; lane holds components {2l, 2l+1}; 8 Lorentz steps
__global__ void time_kernel(const float* __restrict__ b,
                            float* __restrict__ o_out,
                            float* __restrict__ z_out) {
    int warp = (blockIdx.x * blockDim.x + threadIdx.x) >> 5;
    int lane = threadIdx.x & 31;
    if (warp >= NN) return;
    const int n = warp;

    float di = g_dinv[n];
    float sl = di * di;   // self-loop norm
    int c0 = 2 * lane, c1 = c0 + 1;
    size_t base = (size_t)n * OUT_DIM;

    // h = aggregated + self-loop + bias
    float h0 = g_hacc[base + c0] + sl * g_hlin[base + c0] + b[c0];
    float h1 = g_hacc[base + c1] + sl * g_hlin[base + c1] + b[c1];

    float z0 = (lane == 0) ? 1.0f : 0.0f;  // component 0 (time coord) on lane 0
    float z1 = 0.0f;

#pragma unroll
    for (int t = 0; t < TT; t++) {
        // lz = <z,h>_L = sum(z*h) - 2*z[0]*h[0]
        float p = z0 * h0 + z1 * h1;
        float p00 = __shfl_sync(0xffffffffu, z0 * h0, 0);
        float lz = warp_sum(p) - 2.0f * p00;

        // u = h + lz*z  (projection to tangent space)
        float u0 = fmaf(lz, z0, h0);
        float u1 = fmaf(lz, z1, h1);

        // |u|_L^2 = sum(u*u) - 2*u[0]^2
        float q = u0 * u0 + u1 * u1;
        float q00 = __shfl_sync(0xffffffffu, u0 * u0, 0);
        float uu = warp_sum(q) - 2.0f * q00;
        float un = sqrtf(fmaxf(uu, EPS_));

        float ch = coshf(un);
        float sh = sinhf(un) / un;
        z0 = ch * z0 + sh * u0;
        z1 = ch * z1 + sh * u1;

        // membrane potential and spike (match ref ops exactly)
        float znew0 = __shfl_sync(0xffffffffu, z0, 0);
        float v = acoshf(fmaxf(znew0, 1.0f + EPS_));
        bool spike = (v >= 1.0f);
        if (spike) { z0 = (lane == 0) ? 1.0f : 0.0f; z1 = 0.0f; }

        if (lane == 0) o_out[(size_t)t * NN + n] = spike ? 1.0f : 0.0f;
        float2 zz = make_float2(z0, z1);
        *reinterpret_cast<float2*>(z_out + (size_t)t * NN * OUT_DIM + base + c0) = zz;
    }
}

// ---------------- launch ----------------
extern "C" void kernel_launch(void* const* d_in, const int* in_sizes, int n_in,
                              void* d_out, int out_size) {
    const float* x  = (const float*)d_in[0];
    const int*   ei = (const int*)d_in[1];
    const float* W  = (const float*)d_in[2];
    const float* b  = (const float*)d_in[3];

    float* o_out = (float*)d_out;                        // [T, N]
    float* z_out = o_out + (size_t)TT * NN;              // [T, N, 64]

    init_kernel<<<(NN * OUT_DIM + 255) / 256, 256>>>();
    gemm_kernel<<<(NN * 32 + 255) / 256, 256>>>(x, W);
    deg_kernel<<<(EE + 255) / 256, 256>>>(ei);
    dinv_kernel<<<(NN + 255) / 256, 256>>>();
    scatter_kernel<<<(int)(((long long)EE * 16 + 255) / 256), 256>>>(ei);
    time_kernel<<<(NN * 32 + 255) / 256, 256>>>(b, o_out, z_out);
}